// round 14
// baseline (speedup 1.0000x reference)
#include <cuda_runtime.h>
#include <cuda_bf16.h>
#include <cstdint>

#define BB 4
#define CC 512
#define NN 1024
#define HH 8
#define DD 64
#define BHH 32

// ---------------- bf16 hi/lo split scratch (device globals) ----------------
__device__ __nv_bfloat16 g_xh[BB * NN * CC], g_xl[BB * NN * CC];   // xT [b][n][c]
__device__ __nv_bfloat16 g_wh[4 * CC * CC],  g_wl[4 * CC * CC];    // Wq,Wk,Wv,Wo [o][c]
__device__ __nv_bfloat16 g_qh[BHH * NN * DD], g_ql[BHH * NN * DD]; // [bh][i][d]
__device__ __nv_bfloat16 g_kh[BHH * NN * DD], g_kl[BHH * NN * DD]; // [bh][j][d]
__device__ __nv_bfloat16 g_vh[BB * CC * NN],  g_vl[BB * CC * NN];  // [b][o][n] = [bh][d][j]
__device__ __nv_bfloat16 g_yh[BB * NN * CC],  g_yl[BB * NN * CC];  // yT [b][i][c]

// ================= helpers =================
__device__ __forceinline__ uint32_t smem_u32(const void* p) {
    uint32_t a;
    asm("{ .reg .u64 t; cvta.to.shared.u64 t, %1; cvt.u32.u64 %0, t; }" : "=r"(a) : "l"(p));
    return a;
}
__device__ __forceinline__ void cp16(uint32_t dst, const void* src) {
    asm volatile("cp.async.cg.shared.global [%0], [%1], 16;" :: "r"(dst), "l"(src));
}
#define CP_COMMIT()  asm volatile("cp.async.commit_group;")
#define CP_WAIT1()   asm volatile("cp.async.wait_group 1;")
#define BAR_SYNC(id) asm volatile("bar.sync %0, 128;" :: "r"(id) : "memory")
__device__ __forceinline__ void ldmx4(uint32_t r[4], uint32_t addr) {
    asm volatile("ldmatrix.sync.aligned.m8n8.x4.shared.b16 {%0,%1,%2,%3}, [%4];"
                 : "=r"(r[0]), "=r"(r[1]), "=r"(r[2]), "=r"(r[3]) : "r"(addr));
}
__device__ __forceinline__ void mma16816(float c[4], const uint32_t a[4], uint32_t b0, uint32_t b1) {
    asm volatile(
        "mma.sync.aligned.m16n8k16.row.col.f32.bf16.bf16.f32 "
        "{%0,%1,%2,%3}, {%4,%5,%6,%7}, {%8,%9}, {%0,%1,%2,%3};"
        : "+f"(c[0]), "+f"(c[1]), "+f"(c[2]), "+f"(c[3])
        : "r"(a[0]), "r"(a[1]), "r"(a[2]), "r"(a[3]), "r"(b0), "r"(b1));
}
// ldmatrix source address for 16x16 tile at (row0, k0), pitch in bytes
__device__ __forceinline__ uint32_t frag_addr(uint32_t base, int row0, int k0, int pitchB) {
    int lane = threadIdx.x & 31;
    int m = lane >> 3, r = lane & 7;
    int row = row0 + ((m & 1) << 3) + r;
    int k = k0 + ((m >> 1) << 3);
    return base + (uint32_t)(row * pitchB + k * 2);
}
__device__ __forceinline__ void split_pack(float a, float b, uint32_t& hi, uint32_t& lo) {
    __nv_bfloat16 ha = __float2bfloat16(a), hb = __float2bfloat16(b);
    __nv_bfloat16 la = __float2bfloat16(a - __bfloat162float(ha));
    __nv_bfloat16 lb = __float2bfloat16(b - __bfloat162float(hb));
    hi = (uint32_t)__bfloat16_as_ushort(ha) | ((uint32_t)__bfloat16_as_ushort(hb) << 16);
    lo = (uint32_t)__bfloat16_as_ushort(la) | ((uint32_t)__bfloat16_as_ushort(lb) << 16);
}

// ---------------- prep kernels ----------------
__global__ __launch_bounds__(256) void prep_w_kernel(const float* __restrict__ Wq,
                                                     const float* __restrict__ Wk,
                                                     const float* __restrict__ Wv,
                                                     const float* __restrict__ Wo)
{
    int w = blockIdx.y;
    const float* W = (w == 0) ? Wq : (w == 1) ? Wk : (w == 2) ? Wv : Wo;
    int i = (blockIdx.x * 256 + threadIdx.x) * 4;
    float4 v = *(const float4*)(W + i);
    uint32_t h0, l0, h1, l1;
    split_pack(v.x, v.y, h0, l0);
    split_pack(v.z, v.w, h1, l1);
    size_t o = (size_t)w * CC * CC + i;
    *(uint2*)(g_wh + o) = make_uint2(h0, h1);
    *(uint2*)(g_wl + o) = make_uint2(l0, l1);
}

__global__ void prep_x_kernel(const float* __restrict__ x)
{
    __shared__ float t[32][33];
    int b = blockIdx.z;
    int n0 = blockIdx.x << 5, c0 = blockIdx.y << 5;
    int tx = threadIdx.x, ty = threadIdx.y;
    #pragma unroll
    for (int k = 0; k < 4; k++)
        t[ty + k * 8][tx] = x[((size_t)b * CC + c0 + ty + k * 8) * NN + n0 + tx];
    __syncthreads();
    #pragma unroll
    for (int k = 0; k < 4; k++) {
        int n = n0 + ty + k * 8;
        float v = t[tx][ty + k * 8];
        __nv_bfloat16 h = __float2bfloat16(v);
        __nv_bfloat16 l = __float2bfloat16(v - __bfloat162float(h));
        size_t idx = ((size_t)b * NN + n) * CC + c0 + tx;
        g_xh[idx] = h;
        g_xl[idx] = l;
    }
}

// ---------------- shared proj mainloop: c[2][8][4] += W-tile . X-tile ------------
// Tile 128(o) x 128(n), K = 512.
// 2-stage cp.async pipeline. Stage = 40960B: AH@0 AL@10240 BH@20480 BL@30720.
#define PROJ_SMEM 81920

__device__ __forceinline__ void proj_load(uint32_t st,
                                          const __nv_bfloat16* Ah, const __nv_bfloat16* Al,
                                          const __nv_bfloat16* Bh, const __nv_bfloat16* Bl,
                                          int o0, int n0, int k0)
{
    const int tid = threadIdx.x;
    #pragma unroll
    for (int t = tid; t < 512; t += 256) {
        int r = t >> 2, ch = t & 3;
        uint32_t d = (uint32_t)(r * 80 + ch * 16);
        size_t sA = (size_t)(o0 + r) * CC + k0 + ch * 8;
        size_t sB = (size_t)(n0 + r) * CC + k0 + ch * 8;
        cp16(st + 0u     + d, Ah + sA);
        cp16(st + 10240u + d, Al + sA);
        cp16(st + 20480u + d, Bh + sB);
        cp16(st + 30720u + d, Bl + sB);
    }
}

__device__ void proj_gemm(const __nv_bfloat16* Ah, const __nv_bfloat16* Al,
                          const __nv_bfloat16* Bh, const __nv_bfloat16* Bl,
                          int o0, int n0, char* sm, float c[2][8][4])
{
    const int wid = threadIdx.x >> 5;
    const int wm = wid & 3, wn = wid >> 2;
    const uint32_t sb = smem_u32(sm);

    proj_load(sb,          Ah, Al, Bh, Bl, o0, n0, 0);
    CP_COMMIT();
    proj_load(sb + 40960u, Ah, Al, Bh, Bl, o0, n0, 32);
    CP_COMMIT();

    for (int kc = 0; kc < 16; kc++) {
        uint32_t st = sb + (uint32_t)(kc & 1) * 40960u;
        CP_WAIT1();
        __syncthreads();
        #pragma unroll
        for (int ks = 0; ks < 2; ks++) {
            uint32_t ah[2][4], al[2][4];
            ldmx4(ah[0], frag_addr(st + 0u,     wm * 32,      ks * 16, 80));
            ldmx4(ah[1], frag_addr(st + 0u,     wm * 32 + 16, ks * 16, 80));
            ldmx4(al[0], frag_addr(st + 10240u, wm * 32,      ks * 16, 80));
            ldmx4(al[1], frag_addr(st + 10240u, wm * 32 + 16, ks * 16, 80));
            // stream B fragments per 16-col group: low live-register count
            #pragma unroll
            for (int g = 0; g < 4; g++) {
                uint32_t rh[4], rl[4];
                ldmx4(rh, frag_addr(st + 20480u, wn * 64 + g * 16, ks * 16, 80));
                ldmx4(rl, frag_addr(st + 30720u, wn * 64 + g * 16, ks * 16, 80));
                #pragma unroll
                for (int t = 0; t < 2; t++) {
                    int nf = 2 * g + t;
                    #pragma unroll
                    for (int mf = 0; mf < 2; mf++) {
                        mma16816(c[mf][nf], ah[mf], rh[t], rh[t + 2]);
                        mma16816(c[mf][nf], ah[mf], rl[t], rl[t + 2]);
                        mma16816(c[mf][nf], al[mf], rh[t], rh[t + 2]);
                    }
                }
            }
        }
        __syncthreads();
        if (kc + 2 < 16) proj_load(st, Ah, Al, Bh, Bl, o0, n0, (kc + 2) * 32);
        CP_COMMIT();
    }
}

// ---------------- proj QKV ----------------
__global__ __launch_bounds__(256, 2) void proj_qkv_kernel()
{
    extern __shared__ char sm[];
    const int tid = threadIdx.x, lane = tid & 31, wid = tid >> 5;
    const int wm = wid & 3, wn = wid >> 2;
    const int z = blockIdx.z, b = z / 3, mtx = z - b * 3;  // 0=q 1=k 2=v
    const int o0 = blockIdx.y << 7, n0 = blockIdx.x << 7;

    float c[2][8][4] = {};
    proj_gemm(g_wh + (size_t)mtx * CC * CC, g_wl + (size_t)mtx * CC * CC,
              g_xh + (size_t)b * NN * CC, g_xl + (size_t)b * NN * CC,
              o0, n0, sm, c);

    if (mtx == 2) {
        // v: split store [b][o][n]
        #pragma unroll
        for (int mf = 0; mf < 2; mf++)
            #pragma unroll
            for (int nf = 0; nf < 8; nf++) {
                int row = o0 + wm * 32 + mf * 16 + (lane >> 2);
                int col = n0 + wn * 64 + nf * 8 + ((lane & 3) << 1);
                uint32_t hi, lo;
                split_pack(c[mf][nf][0], c[mf][nf][1], hi, lo);
                size_t idx = (size_t)(b * CC + row) * NN + col;
                *(uint32_t*)(g_vh + idx) = hi;
                *(uint32_t*)(g_vl + idx) = lo;
                split_pack(c[mf][nf][2], c[mf][nf][3], hi, lo);
                idx = (size_t)(b * CC + row + 8) * NN + col;
                *(uint32_t*)(g_vh + idx) = hi;
                *(uint32_t*)(g_vl + idx) = lo;
            }
    } else {
        // q/k: transpose via smem, then fully-coalesced split store [bh][i][d]
        float* ep = (float*)sm;
        __syncthreads();
        #pragma unroll
        for (int mf = 0; mf < 2; mf++)
            #pragma unroll
            for (int nf = 0; nf < 8; nf++) {
                int ro = wm * 32 + mf * 16 + (lane >> 2);
                int cn = wn * 64 + nf * 8 + ((lane & 3) << 1);
                ep[cn * 132 + ro]           = c[mf][nf][0];
                ep[(cn + 1) * 132 + ro]     = c[mf][nf][1];
                ep[cn * 132 + ro + 8]       = c[mf][nf][2];
                ep[(cn + 1) * 132 + ro + 8] = c[mf][nf][3];
            }
        __syncthreads();
        __nv_bfloat16* oh = (mtx == 0) ? g_qh : g_kh;
        __nv_bfloat16* ol = (mtx == 0) ? g_ql : g_kl;
        // 8 lanes cover one output row's 64-d range as uint4 chunks (coalesced 128B)
        int chunk = tid & 7;
        #pragma unroll
        for (int it = 0; it < 8; it++) {
            int pr = (tid >> 3) + it * 32;    // 0..255 -> (row, head-half)
            int cn = pr >> 1, half = pr & 1;
            int hh = (o0 >> 6) + half;
            uint32_t vh4[4], vl4[4];
            #pragma unroll
            for (int e = 0; e < 4; e++) {
                float v0 = ep[cn * 132 + half * 64 + chunk * 8 + 2 * e];
                float v1 = ep[cn * 132 + half * 64 + chunk * 8 + 2 * e + 1];
                split_pack(v0, v1, vh4[e], vl4[e]);
            }
            size_t base = ((size_t)(b * HH + hh) * NN + n0 + cn) * DD + chunk * 8;
            *(uint4*)(oh + base) = make_uint4(vh4[0], vh4[1], vh4[2], vh4[3]);
            *(uint4*)(ol + base) = make_uint4(vl4[0], vl4[1], vl4[2], vl4[3]);
        }
    }
}

// ---------------- Wo projection ----------------
__global__ __launch_bounds__(256, 2) void proj_out_kernel(float* __restrict__ out)
{
    extern __shared__ char sm[];
    const int lane = threadIdx.x & 31, wid = threadIdx.x >> 5;
    const int wm = wid & 3, wn = wid >> 2;
    const int b = blockIdx.z;
    const int o0 = blockIdx.y << 7, n0 = blockIdx.x << 7;

    float c[2][8][4] = {};
    proj_gemm(g_wh + (size_t)3 * CC * CC, g_wl + (size_t)3 * CC * CC,
              g_yh + (size_t)b * NN * CC, g_yl + (size_t)b * NN * CC,
              o0, n0, sm, c);

    #pragma unroll
    for (int mf = 0; mf < 2; mf++)
        #pragma unroll
        for (int nf = 0; nf < 8; nf++) {
            int row = o0 + wm * 32 + mf * 16 + (lane >> 2);
            int col = n0 + wn * 64 + nf * 8 + ((lane & 3) << 1);
            *(float2*)(out + (size_t)(b * CC + row) * NN + col) =
                make_float2(c[mf][nf][0], c[mf][nf][1]);
            *(float2*)(out + (size_t)(b * CC + row + 8) * NN + col) =
                make_float2(c[mf][nf][2], c[mf][nf][3]);
        }
}

// ---------------- fused attention: two independent 128-thread halves -------------
// CTA = 256 thr = 2 halves. Half h owns i-rows [i0+64h, i0+64h+64), its own Q tile,
// its own 2 K/V stage buffers, its own cp.async groups, synced only by
// bar.sync(1+h, 128). No __syncthreads -> 4 desynced 128-thr groups per SM keep
// the tensor pipe fed during each other's exp/pack phases.
// smem: Q half h @ h*18432 (QH pitch 144, QL +9216); stages @36864 + (2h+s)*19456:
//   KH +0 (32x144), KL +4608, VH +9216 (64x80), VL +14336
#define A_ST 36864u
#define A_STSZ 19456u
#define ATTN_SMEM (36864 + 4 * 19456)   // 114688

__device__ __forceinline__ void attn_load_kv(uint32_t sb, int half, int s,
                                             int bh, int b, int h, int j0, int htid)
{
    uint32_t st = sb + A_ST + (uint32_t)((half << 1) + s) * A_STSZ;
    #pragma unroll
    for (int t = htid; t < 256; t += 128) {
        int r = t >> 3, ch = t & 7;   // K: 32 j-rows x 8 chunks
        uint32_t d = (uint32_t)(r * 144 + ch * 16);
        size_t srcK = ((size_t)bh * NN + j0 + r) * DD + ch * 8;
        cp16(st + d,         g_kh + srcK);
        cp16(st + 4608u + d, g_kl + srcK);
    }
    #pragma unroll
    for (int t = htid; t < 256; t += 128) {
        int r = t >> 2, ch = t & 3;   // V: 64 d-rows x 4 chunks
        uint32_t d = (uint32_t)(r * 80 + ch * 16);
        size_t srcV = (size_t)(b * CC + h * DD + r) * NN + j0 + ch * 8;
        cp16(st + 9216u + d,  g_vh + srcV);
        cp16(st + 14336u + d, g_vl + srcV);
    }
}

__global__ __launch_bounds__(256, 2) void attn_kernel()
{
    extern __shared__ char sm[];
    const int tid = threadIdx.x, lane = tid & 31;
    const int half = tid >> 7, htid = tid & 127, hwid = htid >> 5;
    const int bh = blockIdx.y, b = bh >> 3, h = bh & 7;
    const int i0h = (blockIdx.x << 7) + half * 64;
    const uint32_t sb = smem_u32(sm);
    const uint32_t qb = sb + (uint32_t)half * 18432u;
    const int barid = 1 + half;

    // prologue: Q tile [64 i][64 d] hi/lo + stage 0 (group 0), stage 1 (group 1)
    #pragma unroll
    for (int t = htid; t < 512; t += 128) {
        int r = t >> 3, ch = t & 7;
        uint32_t d = (uint32_t)(r * 144 + ch * 16);
        size_t src = ((size_t)bh * NN + i0h + r) * DD + ch * 8;
        cp16(qb + d,         g_qh + src);
        cp16(qb + 9216u + d, g_ql + src);
    }
    attn_load_kv(sb, half, 0, bh, b, h, 0, htid);
    CP_COMMIT();
    attn_load_kv(sb, half, 1, bh, b, h, 32, htid);
    CP_COMMIT();

    float yc[8][4] = {};
    float rs0 = 0.f, rs1 = 0.f;
    uint32_t qfh[4][4];

    for (int jb = 0; jb < 32; jb++) {
        uint32_t st = sb + A_ST + (uint32_t)((half << 1) + (jb & 1)) * A_STSZ;
        CP_WAIT1();
        BAR_SYNC(barid);
        if (jb == 0) {
            #pragma unroll
            for (int ks = 0; ks < 4; ks++)
                ldmx4(qfh[ks], frag_addr(qb, hwid * 16, ks * 16, 144));
        }

        // ---- S = Q.K^T for this 32-j stage ----
        float cs[4][4] = {};
        #pragma unroll
        for (int ksd = 0; ksd < 4; ksd++) {
            uint32_t qflc[4];
            ldmx4(qflc, frag_addr(qb + 9216u, hwid * 16, ksd * 16, 144));
            #pragma unroll
            for (int gg = 0; gg < 2; gg++) {
                uint32_t rh[4], rl[4];
                ldmx4(rh, frag_addr(st,         gg * 16, ksd * 16, 144));
                ldmx4(rl, frag_addr(st + 4608u, gg * 16, ksd * 16, 144));
                #pragma unroll
                for (int t = 0; t < 2; t++) {
                    int nf = 2 * gg + t;
                    mma16816(cs[nf], qfh[ksd], rh[t], rh[t + 2]);
                    mma16816(cs[nf], qfh[ksd], rl[t], rl[t + 2]);
                    mma16816(cs[nf], qflc,     rh[t], rh[t + 2]);
                }
            }
        }

        // ---- exp + rowsum + repack into A-fragments ----
        uint32_t aph[2][4], apl[2][4];
        #pragma unroll
        for (int nf = 0; nf < 4; nf++) {
            float p0 = __expf(cs[nf][0]), p1 = __expf(cs[nf][1]);
            float p2 = __expf(cs[nf][2]), p3 = __expf(cs[nf][3]);
            rs0 += p0 + p1;
            rs1 += p2 + p3;
            uint32_t h01, l01, h23, l23;
            split_pack(p0, p1, h01, l01);
            split_pack(p2, p3, h23, l23);
            int kk = nf >> 1, base = (nf & 1) << 1;
            aph[kk][base] = h01; aph[kk][base + 1] = h23;
            apl[kk][base] = l01; apl[kk][base + 1] = l23;
        }

        // ---- Y += P.V^T for this 32-j stage ----
        #pragma unroll
        for (int kk = 0; kk < 2; kk++) {
            #pragma unroll
            for (int gv = 0; gv < 4; gv++) {
                uint32_t vh[4], vl[4];
                ldmx4(vh, frag_addr(st + 9216u,  gv * 16, kk * 16, 80));
                ldmx4(vl, frag_addr(st + 14336u, gv * 16, kk * 16, 80));
                #pragma unroll
                for (int t = 0; t < 2; t++) {
                    int nf = 2 * gv + t;
                    mma16816(yc[nf], aph[kk], vh[t], vh[t + 2]);
                    mma16816(yc[nf], aph[kk], vl[t], vl[t + 2]);
                    mma16816(yc[nf], apl[kk], vh[t], vh[t + 2]);
                }
            }
        }

        BAR_SYNC(barid);
        if (jb + 2 < 32) attn_load_kv(sb, half, jb & 1, bh, b, h, (jb + 2) * 32, htid);
        CP_COMMIT();
    }

    // rowsum: quad reduction (each thread's rows are lane/4 and lane/4+8)
    rs0 += __shfl_xor_sync(0xffffffffu, rs0, 1);
    rs0 += __shfl_xor_sync(0xffffffffu, rs0, 2);
    rs1 += __shfl_xor_sync(0xffffffffu, rs1, 1);
    rs1 += __shfl_xor_sync(0xffffffffu, rs1, 2);
    float inv0 = 1.f / rs0, inv1 = 1.f / rs1;

    int row = i0h + hwid * 16 + (lane >> 2);
    #pragma unroll
    for (int nf = 0; nf < 8; nf++) {
        int d = h * DD + nf * 8 + ((lane & 3) << 1);
        uint32_t hi, lo;
        split_pack(yc[nf][0] * inv0, yc[nf][1] * inv0, hi, lo);
        size_t idx = ((size_t)b * NN + row) * CC + d;
        *(uint32_t*)(g_yh + idx) = hi;
        *(uint32_t*)(g_yl + idx) = lo;
        split_pack(yc[nf][2] * inv1, yc[nf][3] * inv1, hi, lo);
        idx = ((size_t)b * NN + row + 8) * CC + d;
        *(uint32_t*)(g_yh + idx) = hi;
        *(uint32_t*)(g_yl + idx) = lo;
    }
}

// ---------------- entry ----------------------------------------------------------
extern "C" void kernel_launch(void* const* d_in, const int* in_sizes, int n_in,
                              void* d_out, int out_size)
{
    const float* x  = (const float*)d_in[0];
    const float* Wq = (const float*)d_in[1];
    const float* Wk = (const float*)d_in[2];
    const float* Wv = (const float*)d_in[3];
    const float* Wo = (const float*)d_in[4];
    float* out = (float*)d_out;

    cudaFuncSetAttribute(proj_qkv_kernel, cudaFuncAttributeMaxDynamicSharedMemorySize, PROJ_SMEM);
    cudaFuncSetAttribute(proj_out_kernel, cudaFuncAttributeMaxDynamicSharedMemorySize, PROJ_SMEM);
    cudaFuncSetAttribute(attn_kernel,     cudaFuncAttributeMaxDynamicSharedMemorySize, ATTN_SMEM);

    prep_w_kernel<<<dim3(CC * CC / 1024, 4), 256>>>(Wq, Wk, Wv, Wo);
    prep_x_kernel<<<dim3(NN / 32, CC / 32, BB), dim3(32, 8)>>>(x);
    proj_qkv_kernel<<<dim3(NN / 128, CC / 128, BB * 3), 256, PROJ_SMEM>>>();
    attn_kernel<<<dim3(NN / 128, BHH), 256, ATTN_SMEM>>>();
    proj_out_kernel<<<dim3(NN / 128, CC / 128, BB), 256, PROJ_SMEM>>>(out);
}

// round 15
// speedup vs baseline: 1.0212x; 1.0212x over previous
#include <cuda_runtime.h>
#include <cuda_bf16.h>
#include <cstdint>

#define BB 4
#define CC 512
#define NN 1024
#define HH 8
#define DD 64
#define BHH 32

// ---------------- bf16 hi/lo split scratch (device globals) ----------------
__device__ __nv_bfloat16 g_xh[BB * NN * CC], g_xl[BB * NN * CC];   // xT [b][n][c]
__device__ __nv_bfloat16 g_wh[4 * CC * CC],  g_wl[4 * CC * CC];    // Wq,Wk,Wv,Wo [o][c]
__device__ __nv_bfloat16 g_qh[BHH * NN * DD], g_ql[BHH * NN * DD]; // [bh][i][d]
__device__ __nv_bfloat16 g_kh[BHH * NN * DD], g_kl[BHH * NN * DD]; // [bh][j][d]
__device__ __nv_bfloat16 g_vh[BB * CC * NN],  g_vl[BB * CC * NN];  // [b][o][n] = [bh][d][j]
__device__ __nv_bfloat16 g_yh[BB * NN * CC],  g_yl[BB * NN * CC];  // yT [b][i][c]

// ================= helpers =================
__device__ __forceinline__ uint32_t smem_u32(const void* p) {
    uint32_t a;
    asm("{ .reg .u64 t; cvta.to.shared.u64 t, %1; cvt.u32.u64 %0, t; }" : "=r"(a) : "l"(p));
    return a;
}
__device__ __forceinline__ void cp16(uint32_t dst, const void* src) {
    asm volatile("cp.async.cg.shared.global [%0], [%1], 16;" :: "r"(dst), "l"(src));
}
#define CP_COMMIT()  asm volatile("cp.async.commit_group;")
#define CP_WAIT1()   asm volatile("cp.async.wait_group 1;")
#define CP_WAIT2()   asm volatile("cp.async.wait_group 2;")
#define CP_WAIT3()   asm volatile("cp.async.wait_group 3;")
__device__ __forceinline__ void ldmx4(uint32_t r[4], uint32_t addr) {
    asm volatile("ldmatrix.sync.aligned.m8n8.x4.shared.b16 {%0,%1,%2,%3}, [%4];"
                 : "=r"(r[0]), "=r"(r[1]), "=r"(r[2]), "=r"(r[3]) : "r"(addr));
}
__device__ __forceinline__ void mma16816(float c[4], const uint32_t a[4], uint32_t b0, uint32_t b1) {
    asm volatile(
        "mma.sync.aligned.m16n8k16.row.col.f32.bf16.bf16.f32 "
        "{%0,%1,%2,%3}, {%4,%5,%6,%7}, {%8,%9}, {%0,%1,%2,%3};"
        : "+f"(c[0]), "+f"(c[1]), "+f"(c[2]), "+f"(c[3])
        : "r"(a[0]), "r"(a[1]), "r"(a[2]), "r"(a[3]), "r"(b0), "r"(b1));
}
// ldmatrix source address for 16x16 tile at (row0, k0), pitch in bytes
__device__ __forceinline__ uint32_t frag_addr(uint32_t base, int row0, int k0, int pitchB) {
    int lane = threadIdx.x & 31;
    int m = lane >> 3, r = lane & 7;
    int row = row0 + ((m & 1) << 3) + r;
    int k = k0 + ((m >> 1) << 3);
    return base + (uint32_t)(row * pitchB + k * 2);
}
// Fast hi/lo split: 2 packed cvt + 2 bit ops + 2 subs (RNE, identical rounding
// to the scalar version -> bit-identical results, ~half the issue slots).
__device__ __forceinline__ void split_pack(float a, float b, uint32_t& hi, uint32_t& lo) {
    uint32_t h;
    asm("cvt.rn.bf16x2.f32 %0, %1, %2;" : "=r"(h) : "f"(b), "f"(a));   // upper=b, lower=a
    float fa = __uint_as_float(h << 16);
    float fb = __uint_as_float(h & 0xffff0000u);
    float la = a - fa;
    float lb = b - fb;
    uint32_t l;
    asm("cvt.rn.bf16x2.f32 %0, %1, %2;" : "=r"(l) : "f"(lb), "f"(la));
    hi = h; lo = l;
}

// ---------------- prep kernels ----------------
__global__ __launch_bounds__(256) void prep_w_kernel(const float* __restrict__ Wq,
                                                     const float* __restrict__ Wk,
                                                     const float* __restrict__ Wv,
                                                     const float* __restrict__ Wo)
{
    int w = blockIdx.y;
    const float* W = (w == 0) ? Wq : (w == 1) ? Wk : (w == 2) ? Wv : Wo;
    int i = (blockIdx.x * 256 + threadIdx.x) * 4;
    float4 v = *(const float4*)(W + i);
    uint32_t h0, l0, h1, l1;
    split_pack(v.x, v.y, h0, l0);
    split_pack(v.z, v.w, h1, l1);
    size_t o = (size_t)w * CC * CC + i;
    *(uint2*)(g_wh + o) = make_uint2(h0, h1);
    *(uint2*)(g_wl + o) = make_uint2(l0, l1);
}

__global__ void prep_x_kernel(const float* __restrict__ x)
{
    __shared__ float t[32][33];
    int b = blockIdx.z;
    int n0 = blockIdx.x << 5, c0 = blockIdx.y << 5;
    int tx = threadIdx.x, ty = threadIdx.y;
    #pragma unroll
    for (int k = 0; k < 4; k++)
        t[ty + k * 8][tx] = x[((size_t)b * CC + c0 + ty + k * 8) * NN + n0 + tx];
    __syncthreads();
    #pragma unroll
    for (int k = 0; k < 4; k++) {
        int n = n0 + ty + k * 8;
        float v = t[tx][ty + k * 8];
        __nv_bfloat16 h = __float2bfloat16(v);
        __nv_bfloat16 l = __float2bfloat16(v - __bfloat162float(h));
        size_t idx = ((size_t)b * NN + n) * CC + c0 + tx;
        g_xh[idx] = h;
        g_xl[idx] = l;
    }
}

// ---------------- shared proj mainloop: c[2][8][4] += W-tile . X-tile ------------
// Tile 128(o) x 128(n), K = 512.
// 2-stage cp.async pipeline. Stage = 40960B: AH@0 AL@10240 BH@20480 BL@30720.
#define PROJ_SMEM 81920

__device__ __forceinline__ void proj_load(uint32_t st,
                                          const __nv_bfloat16* Ah, const __nv_bfloat16* Al,
                                          const __nv_bfloat16* Bh, const __nv_bfloat16* Bl,
                                          int o0, int n0, int k0)
{
    const int tid = threadIdx.x;
    #pragma unroll
    for (int t = tid; t < 512; t += 256) {
        int r = t >> 2, ch = t & 3;
        uint32_t d = (uint32_t)(r * 80 + ch * 16);
        size_t sA = (size_t)(o0 + r) * CC + k0 + ch * 8;
        size_t sB = (size_t)(n0 + r) * CC + k0 + ch * 8;
        cp16(st + 0u     + d, Ah + sA);
        cp16(st + 10240u + d, Al + sA);
        cp16(st + 20480u + d, Bh + sB);
        cp16(st + 30720u + d, Bl + sB);
    }
}

__device__ void proj_gemm(const __nv_bfloat16* Ah, const __nv_bfloat16* Al,
                          const __nv_bfloat16* Bh, const __nv_bfloat16* Bl,
                          int o0, int n0, char* sm, float c[2][8][4])
{
    const int wid = threadIdx.x >> 5;
    const int wm = wid & 3, wn = wid >> 2;
    const uint32_t sb = smem_u32(sm);

    proj_load(sb,          Ah, Al, Bh, Bl, o0, n0, 0);
    CP_COMMIT();
    proj_load(sb + 40960u, Ah, Al, Bh, Bl, o0, n0, 32);
    CP_COMMIT();

    for (int kc = 0; kc < 16; kc++) {
        uint32_t st = sb + (uint32_t)(kc & 1) * 40960u;
        CP_WAIT1();
        __syncthreads();
        #pragma unroll
        for (int ks = 0; ks < 2; ks++) {
            uint32_t ah[2][4], al[2][4];
            ldmx4(ah[0], frag_addr(st + 0u,     wm * 32,      ks * 16, 80));
            ldmx4(ah[1], frag_addr(st + 0u,     wm * 32 + 16, ks * 16, 80));
            ldmx4(al[0], frag_addr(st + 10240u, wm * 32,      ks * 16, 80));
            ldmx4(al[1], frag_addr(st + 10240u, wm * 32 + 16, ks * 16, 80));
            // stream B fragments per 16-col group: low live-register count
            #pragma unroll
            for (int g = 0; g < 4; g++) {
                uint32_t rh[4], rl[4];
                ldmx4(rh, frag_addr(st + 20480u, wn * 64 + g * 16, ks * 16, 80));
                ldmx4(rl, frag_addr(st + 30720u, wn * 64 + g * 16, ks * 16, 80));
                #pragma unroll
                for (int t = 0; t < 2; t++) {
                    int nf = 2 * g + t;
                    #pragma unroll
                    for (int mf = 0; mf < 2; mf++) {
                        mma16816(c[mf][nf], ah[mf], rh[t], rh[t + 2]);
                        mma16816(c[mf][nf], ah[mf], rl[t], rl[t + 2]);
                        mma16816(c[mf][nf], al[mf], rh[t], rh[t + 2]);
                    }
                }
            }
        }
        __syncthreads();
        if (kc + 2 < 16) proj_load(st, Ah, Al, Bh, Bl, o0, n0, (kc + 2) * 32);
        CP_COMMIT();
    }
}

// ---------------- proj QKV ----------------
__global__ __launch_bounds__(256, 2) void proj_qkv_kernel()
{
    extern __shared__ char sm[];
    const int tid = threadIdx.x, lane = tid & 31, wid = tid >> 5;
    const int wm = wid & 3, wn = wid >> 2;
    const int z = blockIdx.z, b = z / 3, mtx = z - b * 3;  // 0=q 1=k 2=v
    const int o0 = blockIdx.y << 7, n0 = blockIdx.x << 7;

    float c[2][8][4] = {};
    proj_gemm(g_wh + (size_t)mtx * CC * CC, g_wl + (size_t)mtx * CC * CC,
              g_xh + (size_t)b * NN * CC, g_xl + (size_t)b * NN * CC,
              o0, n0, sm, c);

    if (mtx == 2) {
        // v: split store [b][o][n]
        #pragma unroll
        for (int mf = 0; mf < 2; mf++)
            #pragma unroll
            for (int nf = 0; nf < 8; nf++) {
                int row = o0 + wm * 32 + mf * 16 + (lane >> 2);
                int col = n0 + wn * 64 + nf * 8 + ((lane & 3) << 1);
                uint32_t hi, lo;
                split_pack(c[mf][nf][0], c[mf][nf][1], hi, lo);
                size_t idx = (size_t)(b * CC + row) * NN + col;
                *(uint32_t*)(g_vh + idx) = hi;
                *(uint32_t*)(g_vl + idx) = lo;
                split_pack(c[mf][nf][2], c[mf][nf][3], hi, lo);
                idx = (size_t)(b * CC + row + 8) * NN + col;
                *(uint32_t*)(g_vh + idx) = hi;
                *(uint32_t*)(g_vl + idx) = lo;
            }
    } else {
        // q/k: transpose via smem, then fully-coalesced split store [bh][i][d]
        float* ep = (float*)sm;
        __syncthreads();
        #pragma unroll
        for (int mf = 0; mf < 2; mf++)
            #pragma unroll
            for (int nf = 0; nf < 8; nf++) {
                int ro = wm * 32 + mf * 16 + (lane >> 2);
                int cn = wn * 64 + nf * 8 + ((lane & 3) << 1);
                ep[cn * 132 + ro]           = c[mf][nf][0];
                ep[(cn + 1) * 132 + ro]     = c[mf][nf][1];
                ep[cn * 132 + ro + 8]       = c[mf][nf][2];
                ep[(cn + 1) * 132 + ro + 8] = c[mf][nf][3];
            }
        __syncthreads();
        __nv_bfloat16* oh = (mtx == 0) ? g_qh : g_kh;
        __nv_bfloat16* ol = (mtx == 0) ? g_ql : g_kl;
        // 8 lanes cover one output row's 64-d range as uint4 chunks (coalesced 128B)
        int chunk = tid & 7;
        #pragma unroll
        for (int it = 0; it < 8; it++) {
            int pr = (tid >> 3) + it * 32;    // 0..255 -> (row, head-half)
            int cn = pr >> 1, half = pr & 1;
            int hh = (o0 >> 6) + half;
            uint32_t vh4[4], vl4[4];
            #pragma unroll
            for (int e = 0; e < 4; e++) {
                float v0 = ep[cn * 132 + half * 64 + chunk * 8 + 2 * e];
                float v1 = ep[cn * 132 + half * 64 + chunk * 8 + 2 * e + 1];
                split_pack(v0, v1, vh4[e], vl4[e]);
            }
            size_t base = ((size_t)(b * HH + hh) * NN + n0 + cn) * DD + chunk * 8;
            *(uint4*)(oh + base) = make_uint4(vh4[0], vh4[1], vh4[2], vh4[3]);
            *(uint4*)(ol + base) = make_uint4(vl4[0], vl4[1], vl4[2], vl4[3]);
        }
    }
}

// ---------------- Wo projection ----------------
__global__ __launch_bounds__(256, 2) void proj_out_kernel(float* __restrict__ out)
{
    extern __shared__ char sm[];
    const int lane = threadIdx.x & 31, wid = threadIdx.x >> 5;
    const int wm = wid & 3, wn = wid >> 2;
    const int b = blockIdx.z;
    const int o0 = blockIdx.y << 7, n0 = blockIdx.x << 7;

    float c[2][8][4] = {};
    proj_gemm(g_wh + (size_t)3 * CC * CC, g_wl + (size_t)3 * CC * CC,
              g_yh + (size_t)b * NN * CC, g_yl + (size_t)b * NN * CC,
              o0, n0, sm, c);

    #pragma unroll
    for (int mf = 0; mf < 2; mf++)
        #pragma unroll
        for (int nf = 0; nf < 8; nf++) {
            int row = o0 + wm * 32 + mf * 16 + (lane >> 2);
            int col = n0 + wn * 64 + nf * 8 + ((lane & 3) << 1);
            *(float2*)(out + (size_t)(b * CC + row) * NN + col) =
                make_float2(c[mf][nf][0], c[mf][nf][1]);
            *(float2*)(out + (size_t)(b * CC + row + 8) * NN + col) =
                make_float2(c[mf][nf][2], c[mf][nf][3]);
        }
}

// ---------------- fused attention (R9 structure, fast split_pack) ----------------
// Block 256 thr = 8 warps, each warp owns 16 i-rows.
// 4-buffer x 32-j cp.async pipeline. S for stage jb+1 is interleaved with P.V of
// stage jb so every warp always has independent tensor work in flight.
// smem: Q hi/lo @0/18432 (pitch 144), stages @36864 + s*19456:
//   KH +0 (32x144), KL +4608, VH +9216 (64x80), VL +14336
#define A_QH 0u
#define A_QL 18432u
#define A_ST 36864u
#define A_STSZ 19456u
#define ATTN_SMEM (36864 + 4 * 19456)   // 114688

__device__ __forceinline__ void attn_load_kv(uint32_t sb, int s, int bh, int b, int h, int j0)
{
    const int tid = threadIdx.x;
    uint32_t st = sb + A_ST + (uint32_t)s * A_STSZ;
    {   // K tile: 32 j-rows x 64 d (pitch 144), hi/lo
        int r = tid >> 3, ch = tid & 7;
        uint32_t d = (uint32_t)(r * 144 + ch * 16);
        size_t srcK = ((size_t)bh * NN + j0 + r) * DD + ch * 8;
        cp16(st + d,         g_kh + srcK);
        cp16(st + 4608u + d, g_kl + srcK);
    }
    {   // V tile: 64 d-rows x 32 j (pitch 80), hi/lo
        int r = tid >> 2, ch = tid & 3;
        uint32_t d = (uint32_t)(r * 80 + ch * 16);
        size_t srcV = (size_t)(b * CC + h * DD + r) * NN + j0 + ch * 8;
        cp16(st + 9216u + d,  g_vh + srcV);
        cp16(st + 14336u + d, g_vl + srcV);
    }
}

__global__ __launch_bounds__(256, 2) void attn_kernel()
{
    extern __shared__ char sm[];
    const int tid = threadIdx.x, lane = tid & 31, wid = tid >> 5;
    const int bh = blockIdx.y, b = bh >> 3, h = bh & 7;
    const int i0 = blockIdx.x << 7;
    const uint32_t sb = smem_u32(sm);

    // Q tile [128 i][64 d] hi/lo (commit group 1, together with stage 0)
    #pragma unroll
    for (int t = tid; t < 1024; t += 256) {
        int r = t >> 3, ch = t & 7;
        uint32_t d = (uint32_t)(r * 144 + ch * 16);
        size_t src = ((size_t)bh * NN + i0 + r) * DD + ch * 8;
        cp16(sb + A_QH + d, g_qh + src);
        cp16(sb + A_QL + d, g_ql + src);
    }
    attn_load_kv(sb, 0, bh, b, h, 0);
    CP_COMMIT();
    attn_load_kv(sb, 1, bh, b, h, 32);
    CP_COMMIT();
    attn_load_kv(sb, 2, bh, b, h, 64);
    CP_COMMIT();
    attn_load_kv(sb, 3, bh, b, h, 96);
    CP_COMMIT();

    float yc[8][4] = {};
    float cs[4][4] = {};
    float rs0 = 0.f, rs1 = 0.f;
    uint32_t qfh[4][4], qflc[4];
    uint32_t khb[2][4], klb[2][4];

    // ---- prologue: wait stage 0 + Q, load Q-hi frags, compute S_0 ----
    CP_WAIT3();
    __syncthreads();
    #pragma unroll
    for (int ks = 0; ks < 4; ks++)
        ldmx4(qfh[ks], frag_addr(sb + A_QH, wid * 16, ks * 16, 144));
    {
        uint32_t st0 = sb + A_ST;
        ldmx4(khb[0], frag_addr(st0,         0, 0, 144));
        ldmx4(klb[0], frag_addr(st0 + 4608u, 0, 0, 144));
        #pragma unroll
        for (int u = 0; u < 8; u++) {
            const int ksd = u >> 1, gg = u & 1;
            if (gg == 0) ldmx4(qflc, frag_addr(sb + A_QL, wid * 16, ksd * 16, 144));
            if (u < 7) {
                const int k2 = (u + 1) >> 1, g2 = (u + 1) & 1;
                ldmx4(khb[(u + 1) & 1], frag_addr(st0,         g2 * 16, k2 * 16, 144));
                ldmx4(klb[(u + 1) & 1], frag_addr(st0 + 4608u, g2 * 16, k2 * 16, 144));
            }
            #pragma unroll
            for (int t = 0; t < 2; t++) {
                int nf = 2 * gg + t;
                mma16816(cs[nf], qfh[ksd], khb[u & 1][t], khb[u & 1][t + 2]);
                mma16816(cs[nf], qfh[ksd], klb[u & 1][t], klb[u & 1][t + 2]);
                mma16816(cs[nf], qflc,     khb[u & 1][t], khb[u & 1][t + 2]);
            }
        }
    }

    // ---- main loop: iter jb does exp(S_jb), then PV_jb interleaved with S_{jb+1} --
    for (int jb = 0; jb < 31; jb++) {
        uint32_t aph[2][4], apl[2][4];
        #pragma unroll
        for (int nf = 0; nf < 4; nf++) {
            float p0 = __expf(cs[nf][0]), p1 = __expf(cs[nf][1]);
            float p2 = __expf(cs[nf][2]), p3 = __expf(cs[nf][3]);
            rs0 += p0 + p1;
            rs1 += p2 + p3;
            uint32_t h01, l01, h23, l23;
            split_pack(p0, p1, h01, l01);
            split_pack(p2, p3, h23, l23);
            int kk = nf >> 1, base = (nf & 1) << 1;
            aph[kk][base] = h01; aph[kk][base + 1] = h23;
            apl[kk][base] = l01; apl[kk][base + 1] = l23;
            cs[nf][0] = 0.f; cs[nf][1] = 0.f; cs[nf][2] = 0.f; cs[nf][3] = 0.f;
        }
        CP_WAIT2();
        __syncthreads();
        uint32_t stN = sb + A_ST + (uint32_t)((jb + 1) & 3) * A_STSZ;  // K_{jb+1}
        uint32_t stV = sb + A_ST + (uint32_t)(jb & 3) * A_STSZ;        // V_jb

        ldmx4(khb[0], frag_addr(stN,         0, 0, 144));
        ldmx4(klb[0], frag_addr(stN + 4608u, 0, 0, 144));
        #pragma unroll
        for (int u = 0; u < 8; u++) {
            const int ksd = u >> 1, gg = u & 1;   // S pair (K frags)
            const int kk = u >> 2, gv = u & 3;    // PV pair (V frags)
            uint32_t vh[4], vl[4];
            ldmx4(vh, frag_addr(stV + 9216u,  gv * 16, kk * 16, 80));
            ldmx4(vl, frag_addr(stV + 14336u, gv * 16, kk * 16, 80));
            if (gg == 0) ldmx4(qflc, frag_addr(sb + A_QL, wid * 16, ksd * 16, 144));
            // S_{jb+1}
            #pragma unroll
            for (int t = 0; t < 2; t++) {
                int nf = 2 * gg + t;
                mma16816(cs[nf], qfh[ksd], khb[u & 1][t], khb[u & 1][t + 2]);
                mma16816(cs[nf], qfh[ksd], klb[u & 1][t], klb[u & 1][t + 2]);
                mma16816(cs[nf], qflc,     khb[u & 1][t], khb[u & 1][t + 2]);
            }
            if (u < 7) {
                const int k2 = (u + 1) >> 1, g2 = (u + 1) & 1;
                ldmx4(khb[(u + 1) & 1], frag_addr(stN,         g2 * 16, k2 * 16, 144));
                ldmx4(klb[(u + 1) & 1], frag_addr(stN + 4608u, g2 * 16, k2 * 16, 144));
            }
            // PV_jb
            #pragma unroll
            for (int t = 0; t < 2; t++) {
                int nf = 2 * gv + t;
                mma16816(yc[nf], aph[kk], vh[t], vh[t + 2]);
                mma16816(yc[nf], aph[kk], vl[t], vl[t + 2]);
                mma16816(yc[nf], apl[kk], vh[t], vh[t + 2]);
            }
        }
        __syncthreads();
        if (jb + 4 < 32) attn_load_kv(sb, jb & 3, bh, b, h, (jb + 4) * 32);
        CP_COMMIT();
    }

    // ---- final iteration (jb = 31): exp + PV only ----
    {
        uint32_t aph[2][4], apl[2][4];
        #pragma unroll
        for (int nf = 0; nf < 4; nf++) {
            float p0 = __expf(cs[nf][0]), p1 = __expf(cs[nf][1]);
            float p2 = __expf(cs[nf][2]), p3 = __expf(cs[nf][3]);
            rs0 += p0 + p1;
            rs1 += p2 + p3;
            uint32_t h01, l01, h23, l23;
            split_pack(p0, p1, h01, l01);
            split_pack(p2, p3, h23, l23);
            int kk = nf >> 1, base = (nf & 1) << 1;
            aph[kk][base] = h01; aph[kk][base + 1] = h23;
            apl[kk][base] = l01; apl[kk][base + 1] = l23;
        }
        CP_WAIT2();
        __syncthreads();
        uint32_t stV = sb + A_ST + (uint32_t)(31 & 3) * A_STSZ;
        uint32_t vhb[2][4], vlb[2][4];
        ldmx4(vhb[0], frag_addr(stV + 9216u,  0, 0, 80));
        ldmx4(vlb[0], frag_addr(stV + 14336u, 0, 0, 80));
        #pragma unroll
        for (int u = 0; u < 8; u++) {
            const int kk = u >> 2, gv = u & 3;
            if (u < 7) {
                const int k2 = (u + 1) >> 2, g2 = (u + 1) & 3;
                ldmx4(vhb[(u + 1) & 1], frag_addr(stV + 9216u,  g2 * 16, k2 * 16, 80));
                ldmx4(vlb[(u + 1) & 1], frag_addr(stV + 14336u, g2 * 16, k2 * 16, 80));
            }
            #pragma unroll
            for (int t = 0; t < 2; t++) {
                int nf = 2 * gv + t;
                mma16816(yc[nf], aph[kk], vhb[u & 1][t], vhb[u & 1][t + 2]);
                mma16816(yc[nf], aph[kk], vlb[u & 1][t], vlb[u & 1][t + 2]);
                mma16816(yc[nf], apl[kk], vhb[u & 1][t], vhb[u & 1][t + 2]);
            }
        }
    }

    // rowsum: quad reduction (each thread's rows are lane/4 and lane/4+8)
    rs0 += __shfl_xor_sync(0xffffffffu, rs0, 1);
    rs0 += __shfl_xor_sync(0xffffffffu, rs0, 2);
    rs1 += __shfl_xor_sync(0xffffffffu, rs1, 1);
    rs1 += __shfl_xor_sync(0xffffffffu, rs1, 2);
    float inv0 = 1.f / rs0, inv1 = 1.f / rs1;

    int row = i0 + wid * 16 + (lane >> 2);
    #pragma unroll
    for (int nf = 0; nf < 8; nf++) {
        int d = h * DD + nf * 8 + ((lane & 3) << 1);
        uint32_t hi, lo;
        split_pack(yc[nf][0] * inv0, yc[nf][1] * inv0, hi, lo);
        size_t idx = ((size_t)b * NN + row) * CC + d;
        *(uint32_t*)(g_yh + idx) = hi;
        *(uint32_t*)(g_yl + idx) = lo;
        split_pack(yc[nf][2] * inv1, yc[nf][3] * inv1, hi, lo);
        idx = ((size_t)b * NN + row + 8) * CC + d;
        *(uint32_t*)(g_yh + idx) = hi;
        *(uint32_t*)(g_yl + idx) = lo;
    }
}

// ---------------- entry ----------------------------------------------------------
extern "C" void kernel_launch(void* const* d_in, const int* in_sizes, int n_in,
                              void* d_out, int out_size)
{
    const float* x  = (const float*)d_in[0];
    const float* Wq = (const float*)d_in[1];
    const float* Wk = (const float*)d_in[2];
    const float* Wv = (const float*)d_in[3];
    const float* Wo = (const float*)d_in[4];
    float* out = (float*)d_out;

    cudaFuncSetAttribute(proj_qkv_kernel, cudaFuncAttributeMaxDynamicSharedMemorySize, PROJ_SMEM);
    cudaFuncSetAttribute(proj_out_kernel, cudaFuncAttributeMaxDynamicSharedMemorySize, PROJ_SMEM);
    cudaFuncSetAttribute(attn_kernel,     cudaFuncAttributeMaxDynamicSharedMemorySize, ATTN_SMEM);

    prep_w_kernel<<<dim3(CC * CC / 1024, 4), 256>>>(Wq, Wk, Wv, Wo);
    prep_x_kernel<<<dim3(NN / 32, CC / 32, BB), dim3(32, 8)>>>(x);
    proj_qkv_kernel<<<dim3(NN / 128, CC / 128, BB * 3), 256, PROJ_SMEM>>>();
    attn_kernel<<<dim3(NN / 128, BHH), 256, ATTN_SMEM>>>();
    proj_out_kernel<<<dim3(NN / 128, CC / 128, BB), 256, PROJ_SMEM>>>(out);
}

// round 16
// speedup vs baseline: 1.0555x; 1.0337x over previous
#include <cuda_runtime.h>
#include <cuda_bf16.h>
#include <cuda_fp16.h>
#include <cstdint>

#define BB 4
#define CC 512
#define NN 1024
#define HH 8
#define DD 64
#define BHH 32

// ---------------- scratch (device globals) ----------------
__device__ __nv_bfloat16 g_xh[BB * NN * CC], g_xl[BB * NN * CC];   // xT [b][n][c]
__device__ __nv_bfloat16 g_wh[3 * CC * CC],  g_wl[3 * CC * CC];    // Wq,Wk,Wv [o][c] bf16 hi/lo
__device__ __half        g_woh[CC * CC];                           // Wo [o][c] fp16 hi only
__device__ __nv_bfloat16 g_qh[BHH * NN * DD], g_ql[BHH * NN * DD]; // [bh][i][d] (q pre-scaled by log2e)
__device__ __nv_bfloat16 g_kh[BHH * NN * DD], g_kl[BHH * NN * DD]; // [bh][j][d]
__device__ __nv_bfloat16 g_vh[BB * CC * NN],  g_vl[BB * CC * NN];  // [b][o][n] = [bh][d][j]
__device__ __half        g_yh[BB * NN * CC],  g_yl[BB * NN * CC];  // yT [b][i][c] fp16 hi/lo

// ================= helpers =================
__device__ __forceinline__ uint32_t smem_u32(const void* p) {
    uint32_t a;
    asm("{ .reg .u64 t; cvta.to.shared.u64 t, %1; cvt.u32.u64 %0, t; }" : "=r"(a) : "l"(p));
    return a;
}
__device__ __forceinline__ void cp16(uint32_t dst, const void* src) {
    asm volatile("cp.async.cg.shared.global [%0], [%1], 16;" :: "r"(dst), "l"(src));
}
#define CP_COMMIT()  asm volatile("cp.async.commit_group;")
#define CP_WAIT1()   asm volatile("cp.async.wait_group 1;")
#define CP_WAIT2()   asm volatile("cp.async.wait_group 2;")
#define CP_WAIT3()   asm volatile("cp.async.wait_group 3;")
__device__ __forceinline__ void ldmx4(uint32_t r[4], uint32_t addr) {
    asm volatile("ldmatrix.sync.aligned.m8n8.x4.shared.b16 {%0,%1,%2,%3}, [%4];"
                 : "=r"(r[0]), "=r"(r[1]), "=r"(r[2]), "=r"(r[3]) : "r"(addr));
}
__device__ __forceinline__ void mma16816(float c[4], const uint32_t a[4], uint32_t b0, uint32_t b1) {
    asm volatile(
        "mma.sync.aligned.m16n8k16.row.col.f32.bf16.bf16.f32 "
        "{%0,%1,%2,%3}, {%4,%5,%6,%7}, {%8,%9}, {%0,%1,%2,%3};"
        : "+f"(c[0]), "+f"(c[1]), "+f"(c[2]), "+f"(c[3])
        : "r"(a[0]), "r"(a[1]), "r"(a[2]), "r"(a[3]), "r"(b0), "r"(b1));
}
__device__ __forceinline__ void mma16816h(float c[4], const uint32_t a[4], uint32_t b0, uint32_t b1) {
    asm volatile(
        "mma.sync.aligned.m16n8k16.row.col.f32.f16.f16.f32 "
        "{%0,%1,%2,%3}, {%4,%5,%6,%7}, {%8,%9}, {%0,%1,%2,%3};"
        : "+f"(c[0]), "+f"(c[1]), "+f"(c[2]), "+f"(c[3])
        : "r"(a[0]), "r"(a[1]), "r"(a[2]), "r"(a[3]), "r"(b0), "r"(b1));
}
// ldmatrix source address for 16x16 tile at (row0, k0), pitch in bytes
__device__ __forceinline__ uint32_t frag_addr(uint32_t base, int row0, int k0, int pitchB) {
    int lane = threadIdx.x & 31;
    int m = lane >> 3, r = lane & 7;
    int row = row0 + ((m & 1) << 3) + r;
    int k = k0 + ((m >> 1) << 3);
    return base + (uint32_t)(row * pitchB + k * 2);
}
// Fast bf16 hi/lo split: 2 packed cvt + 2 bit ops + 2 subs (RNE)
__device__ __forceinline__ void split_pack(float a, float b, uint32_t& hi, uint32_t& lo) {
    uint32_t h;
    asm("cvt.rn.bf16x2.f32 %0, %1, %2;" : "=r"(h) : "f"(b), "f"(a));   // upper=b, lower=a
    float fa = __uint_as_float(h << 16);
    float fb = __uint_as_float(h & 0xffff0000u);
    float la = a - fa;
    float lb = b - fb;
    uint32_t l;
    asm("cvt.rn.bf16x2.f32 %0, %1, %2;" : "=r"(l) : "f"(lb), "f"(la));
    hi = h; lo = l;
}
// fp16 hi/lo split (RNE)
__device__ __forceinline__ void split_pack_f16(float a, float b, uint32_t& hi, uint32_t& lo) {
    uint32_t h;
    asm("cvt.rn.f16x2.f32 %0, %1, %2;" : "=r"(h) : "f"(b), "f"(a));    // upper=b, lower=a
    float fa, fb;
    asm("{\n\t.reg .b16 x, y;\n\tmov.b32 {x, y}, %2;\n\t"
        "cvt.f32.f16 %0, x;\n\tcvt.f32.f16 %1, y;\n\t}"
        : "=f"(fa), "=f"(fb) : "r"(h));
    float la = a - fa;
    float lb = b - fb;
    uint32_t l;
    asm("cvt.rn.f16x2.f32 %0, %1, %2;" : "=r"(l) : "f"(lb), "f"(la));
    hi = h; lo = l;
}
__device__ __forceinline__ float ex2f(float x) {
    float r;
    asm("ex2.approx.f32 %0, %1;" : "=f"(r) : "f"(x));
    return r;
}
#define LOG2E 1.4426950408889634f

// ---------------- prep kernels ----------------
__global__ __launch_bounds__(256) void prep_w_kernel(const float* __restrict__ Wq,
                                                     const float* __restrict__ Wk,
                                                     const float* __restrict__ Wv,
                                                     const float* __restrict__ Wo)
{
    int w = blockIdx.y;
    const float* W = (w == 0) ? Wq : (w == 1) ? Wk : (w == 2) ? Wv : Wo;
    int i = (blockIdx.x * 256 + threadIdx.x) * 4;
    float4 v = *(const float4*)(W + i);
    if (w < 3) {
        uint32_t h0, l0, h1, l1;
        split_pack(v.x, v.y, h0, l0);
        split_pack(v.z, v.w, h1, l1);
        size_t o = (size_t)w * CC * CC + i;
        *(uint2*)(g_wh + o) = make_uint2(h0, h1);
        *(uint2*)(g_wl + o) = make_uint2(l0, l1);
    } else {
        uint32_t h0, h1;
        asm("cvt.rn.f16x2.f32 %0, %1, %2;" : "=r"(h0) : "f"(v.y), "f"(v.x));
        asm("cvt.rn.f16x2.f32 %0, %1, %2;" : "=r"(h1) : "f"(v.w), "f"(v.z));
        *(uint2*)(g_woh + i) = make_uint2(h0, h1);
    }
}

__global__ void prep_x_kernel(const float* __restrict__ x)
{
    __shared__ float t[32][33];
    int b = blockIdx.z;
    int n0 = blockIdx.x << 5, c0 = blockIdx.y << 5;
    int tx = threadIdx.x, ty = threadIdx.y;
    #pragma unroll
    for (int k = 0; k < 4; k++)
        t[ty + k * 8][tx] = x[((size_t)b * CC + c0 + ty + k * 8) * NN + n0 + tx];
    __syncthreads();
    #pragma unroll
    for (int k = 0; k < 4; k++) {
        int n = n0 + ty + k * 8;
        float v = t[tx][ty + k * 8];
        __nv_bfloat16 h = __float2bfloat16(v);
        __nv_bfloat16 l = __float2bfloat16(v - __bfloat162float(h));
        size_t idx = ((size_t)b * NN + n) * CC + c0 + tx;
        g_xh[idx] = h;
        g_xl[idx] = l;
    }
}

// ---------------- shared proj mainloop (3xBF16): c[2][8][4] += W . X -------------
// Tile 128(o) x 128(n), K = 512.
// 2-stage cp.async pipeline. Stage = 40960B: AH@0 AL@10240 BH@20480 BL@30720.
#define PROJ_SMEM 81920

__device__ __forceinline__ void proj_load(uint32_t st,
                                          const __nv_bfloat16* Ah, const __nv_bfloat16* Al,
                                          const __nv_bfloat16* Bh, const __nv_bfloat16* Bl,
                                          int o0, int n0, int k0)
{
    const int tid = threadIdx.x;
    #pragma unroll
    for (int t = tid; t < 512; t += 256) {
        int r = t >> 2, ch = t & 3;
        uint32_t d = (uint32_t)(r * 80 + ch * 16);
        size_t sA = (size_t)(o0 + r) * CC + k0 + ch * 8;
        size_t sB = (size_t)(n0 + r) * CC + k0 + ch * 8;
        cp16(st + 0u     + d, Ah + sA);
        cp16(st + 10240u + d, Al + sA);
        cp16(st + 20480u + d, Bh + sB);
        cp16(st + 30720u + d, Bl + sB);
    }
}

__device__ void proj_gemm(const __nv_bfloat16* Ah, const __nv_bfloat16* Al,
                          const __nv_bfloat16* Bh, const __nv_bfloat16* Bl,
                          int o0, int n0, char* sm, float c[2][8][4])
{
    const int wid = threadIdx.x >> 5;
    const int wm = wid & 3, wn = wid >> 2;
    const uint32_t sb = smem_u32(sm);

    proj_load(sb,          Ah, Al, Bh, Bl, o0, n0, 0);
    CP_COMMIT();
    proj_load(sb + 40960u, Ah, Al, Bh, Bl, o0, n0, 32);
    CP_COMMIT();

    for (int kc = 0; kc < 16; kc++) {
        uint32_t st = sb + (uint32_t)(kc & 1) * 40960u;
        CP_WAIT1();
        __syncthreads();
        #pragma unroll
        for (int ks = 0; ks < 2; ks++) {
            uint32_t ah[2][4], al[2][4];
            ldmx4(ah[0], frag_addr(st + 0u,     wm * 32,      ks * 16, 80));
            ldmx4(ah[1], frag_addr(st + 0u,     wm * 32 + 16, ks * 16, 80));
            ldmx4(al[0], frag_addr(st + 10240u, wm * 32,      ks * 16, 80));
            ldmx4(al[1], frag_addr(st + 10240u, wm * 32 + 16, ks * 16, 80));
            #pragma unroll
            for (int g = 0; g < 4; g++) {
                uint32_t rh[4], rl[4];
                ldmx4(rh, frag_addr(st + 20480u, wn * 64 + g * 16, ks * 16, 80));
                ldmx4(rl, frag_addr(st + 30720u, wn * 64 + g * 16, ks * 16, 80));
                #pragma unroll
                for (int t = 0; t < 2; t++) {
                    int nf = 2 * g + t;
                    #pragma unroll
                    for (int mf = 0; mf < 2; mf++) {
                        mma16816(c[mf][nf], ah[mf], rh[t], rh[t + 2]);
                        mma16816(c[mf][nf], ah[mf], rl[t], rl[t + 2]);
                        mma16816(c[mf][nf], al[mf], rh[t], rh[t + 2]);
                    }
                }
            }
        }
        __syncthreads();
        if (kc + 2 < 16) proj_load(st, Ah, Al, Bh, Bl, o0, n0, (kc + 2) * 32);
        CP_COMMIT();
    }
}

// ---------------- proj QKV ----------------
__global__ __launch_bounds__(256, 2) void proj_qkv_kernel()
{
    extern __shared__ char sm[];
    const int tid = threadIdx.x, lane = tid & 31, wid = tid >> 5;
    const int wm = wid & 3, wn = wid >> 2;
    const int z = blockIdx.z, b = z / 3, mtx = z - b * 3;  // 0=q 1=k 2=v
    const int o0 = blockIdx.y << 7, n0 = blockIdx.x << 7;

    float c[2][8][4] = {};
    proj_gemm(g_wh + (size_t)mtx * CC * CC, g_wl + (size_t)mtx * CC * CC,
              g_xh + (size_t)b * NN * CC, g_xl + (size_t)b * NN * CC,
              o0, n0, sm, c);

    if (mtx == 2) {
        // v: split store [b][o][n]
        #pragma unroll
        for (int mf = 0; mf < 2; mf++)
            #pragma unroll
            for (int nf = 0; nf < 8; nf++) {
                int row = o0 + wm * 32 + mf * 16 + (lane >> 2);
                int col = n0 + wn * 64 + nf * 8 + ((lane & 3) << 1);
                uint32_t hi, lo;
                split_pack(c[mf][nf][0], c[mf][nf][1], hi, lo);
                size_t idx = (size_t)(b * CC + row) * NN + col;
                *(uint32_t*)(g_vh + idx) = hi;
                *(uint32_t*)(g_vl + idx) = lo;
                split_pack(c[mf][nf][2], c[mf][nf][3], hi, lo);
                idx = (size_t)(b * CC + row + 8) * NN + col;
                *(uint32_t*)(g_vh + idx) = hi;
                *(uint32_t*)(g_vl + idx) = lo;
            }
    } else {
        // q/k: transpose via smem, then fully-coalesced split store [bh][i][d]
        // q is pre-scaled by log2(e) so attention can use bare ex2.
        const float scl = (mtx == 0) ? LOG2E : 1.0f;
        float* ep = (float*)sm;
        __syncthreads();
        #pragma unroll
        for (int mf = 0; mf < 2; mf++)
            #pragma unroll
            for (int nf = 0; nf < 8; nf++) {
                int ro = wm * 32 + mf * 16 + (lane >> 2);
                int cn = wn * 64 + nf * 8 + ((lane & 3) << 1);
                ep[cn * 132 + ro]           = c[mf][nf][0] * scl;
                ep[(cn + 1) * 132 + ro]     = c[mf][nf][1] * scl;
                ep[cn * 132 + ro + 8]       = c[mf][nf][2] * scl;
                ep[(cn + 1) * 132 + ro + 8] = c[mf][nf][3] * scl;
            }
        __syncthreads();
        __nv_bfloat16* oh = (mtx == 0) ? g_qh : g_kh;
        __nv_bfloat16* ol = (mtx == 0) ? g_ql : g_kl;
        int chunk = tid & 7;
        #pragma unroll
        for (int it = 0; it < 8; it++) {
            int pr = (tid >> 3) + it * 32;    // 0..255 -> (row, head-half)
            int cn = pr >> 1, half = pr & 1;
            int hh = (o0 >> 6) + half;
            uint32_t vh4[4], vl4[4];
            #pragma unroll
            for (int e = 0; e < 4; e++) {
                float v0 = ep[cn * 132 + half * 64 + chunk * 8 + 2 * e];
                float v1 = ep[cn * 132 + half * 64 + chunk * 8 + 2 * e + 1];
                split_pack(v0, v1, vh4[e], vl4[e]);
            }
            size_t base = ((size_t)(b * HH + hh) * NN + n0 + cn) * DD + chunk * 8;
            *(uint4*)(oh + base) = make_uint4(vh4[0], vh4[1], vh4[2], vh4[3]);
            *(uint4*)(ol + base) = make_uint4(vl4[0], vl4[1], vl4[2], vl4[3]);
        }
    }
}

// ---------------- Wo projection (2xFP16: Wo_hi.y_hi + Wo_hi.y_lo) ----------------
// Stage = 30720B: AH@0 (128x80) BH@10240 (128x80) BL@20480.
#define POUT_SMEM (2 * 30720)

__device__ __forceinline__ void pout_load(uint32_t st, const __half* Ah,
                                          const __half* Bh, const __half* Bl,
                                          int o0, int n0, int k0)
{
    const int tid = threadIdx.x;
    #pragma unroll
    for (int t = tid; t < 512; t += 256) {
        int r = t >> 2, ch = t & 3;
        uint32_t d = (uint32_t)(r * 80 + ch * 16);
        cp16(st + d, Ah + (size_t)(o0 + r) * CC + k0 + ch * 8);
        size_t sB = (size_t)(n0 + r) * CC + k0 + ch * 8;
        cp16(st + 10240u + d, Bh + sB);
        cp16(st + 20480u + d, Bl + sB);
    }
}

__global__ __launch_bounds__(256, 2) void proj_out_kernel(float* __restrict__ out)
{
    extern __shared__ char sm[];
    const int tid = threadIdx.x, lane = tid & 31, wid = tid >> 5;
    const int wm = wid & 3, wn = wid >> 2;
    const int b = blockIdx.z;
    const int o0 = blockIdx.y << 7, n0 = blockIdx.x << 7;
    const __half* Ah = g_woh;
    const __half* Bh = g_yh + (size_t)b * NN * CC;
    const __half* Bl = g_yl + (size_t)b * NN * CC;
    const uint32_t sb = smem_u32(sm);

    pout_load(sb,          Ah, Bh, Bl, o0, n0, 0);
    CP_COMMIT();
    pout_load(sb + 30720u, Ah, Bh, Bl, o0, n0, 32);
    CP_COMMIT();

    float c[2][8][4] = {};
    for (int kc = 0; kc < 16; kc++) {
        uint32_t st = sb + (uint32_t)(kc & 1) * 30720u;
        CP_WAIT1();
        __syncthreads();
        #pragma unroll
        for (int ks = 0; ks < 2; ks++) {
            uint32_t ah[2][4];
            ldmx4(ah[0], frag_addr(st, wm * 32,      ks * 16, 80));
            ldmx4(ah[1], frag_addr(st, wm * 32 + 16, ks * 16, 80));
            #pragma unroll
            for (int g = 0; g < 4; g++) {
                uint32_t rh[4], rl[4];
                ldmx4(rh, frag_addr(st + 10240u, wn * 64 + g * 16, ks * 16, 80));
                ldmx4(rl, frag_addr(st + 20480u, wn * 64 + g * 16, ks * 16, 80));
                #pragma unroll
                for (int t = 0; t < 2; t++) {
                    int nf = 2 * g + t;
                    #pragma unroll
                    for (int mf = 0; mf < 2; mf++) {
                        mma16816h(c[mf][nf], ah[mf], rh[t], rh[t + 2]);
                        mma16816h(c[mf][nf], ah[mf], rl[t], rl[t + 2]);
                    }
                }
            }
        }
        __syncthreads();
        if (kc + 2 < 16) pout_load(st, Ah, Bh, Bl, o0, n0, (kc + 2) * 32);
        CP_COMMIT();
    }

    #pragma unroll
    for (int mf = 0; mf < 2; mf++)
        #pragma unroll
        for (int nf = 0; nf < 8; nf++) {
            int row = o0 + wm * 32 + mf * 16 + (lane >> 2);
            int col = n0 + wn * 64 + nf * 8 + ((lane & 3) << 1);
            *(float2*)(out + (size_t)(b * CC + row) * NN + col) =
                make_float2(c[mf][nf][0], c[mf][nf][1]);
            *(float2*)(out + (size_t)(b * CC + row + 8) * NN + col) =
                make_float2(c[mf][nf][2], c[mf][nf][3]);
        }
}

// ---------------- fused attention (R15 structure, ex2 + fp16 y epilogue) ---------
#define A_QH 0u
#define A_QL 18432u
#define A_ST 36864u
#define A_STSZ 19456u
#define ATTN_SMEM (36864 + 4 * 19456)   // 114688

__device__ __forceinline__ void attn_load_kv(uint32_t sb, int s, int bh, int b, int h, int j0)
{
    const int tid = threadIdx.x;
    uint32_t st = sb + A_ST + (uint32_t)s * A_STSZ;
    {   // K tile: 32 j-rows x 64 d (pitch 144), hi/lo
        int r = tid >> 3, ch = tid & 7;
        uint32_t d = (uint32_t)(r * 144 + ch * 16);
        size_t srcK = ((size_t)bh * NN + j0 + r) * DD + ch * 8;
        cp16(st + d,         g_kh + srcK);
        cp16(st + 4608u + d, g_kl + srcK);
    }
    {   // V tile: 64 d-rows x 32 j (pitch 80), hi/lo
        int r = tid >> 2, ch = tid & 3;
        uint32_t d = (uint32_t)(r * 80 + ch * 16);
        size_t srcV = (size_t)(b * CC + h * DD + r) * NN + j0 + ch * 8;
        cp16(st + 9216u + d,  g_vh + srcV);
        cp16(st + 14336u + d, g_vl + srcV);
    }
}

__global__ __launch_bounds__(256, 2) void attn_kernel()
{
    extern __shared__ char sm[];
    const int tid = threadIdx.x, lane = tid & 31, wid = tid >> 5;
    const int bh = blockIdx.y, b = bh >> 3, h = bh & 7;
    const int i0 = blockIdx.x << 7;
    const uint32_t sb = smem_u32(sm);

    #pragma unroll
    for (int t = tid; t < 1024; t += 256) {
        int r = t >> 3, ch = t & 7;
        uint32_t d = (uint32_t)(r * 144 + ch * 16);
        size_t src = ((size_t)bh * NN + i0 + r) * DD + ch * 8;
        cp16(sb + A_QH + d, g_qh + src);
        cp16(sb + A_QL + d, g_ql + src);
    }
    attn_load_kv(sb, 0, bh, b, h, 0);
    CP_COMMIT();
    attn_load_kv(sb, 1, bh, b, h, 32);
    CP_COMMIT();
    attn_load_kv(sb, 2, bh, b, h, 64);
    CP_COMMIT();
    attn_load_kv(sb, 3, bh, b, h, 96);
    CP_COMMIT();

    float yc[8][4] = {};
    float cs[4][4] = {};
    float rs0 = 0.f, rs1 = 0.f;
    uint32_t qfh[4][4], qflc[4];
    uint32_t khb[2][4], klb[2][4];

    // ---- prologue: wait stage 0 + Q, load Q-hi frags, compute S_0 ----
    CP_WAIT3();
    __syncthreads();
    #pragma unroll
    for (int ks = 0; ks < 4; ks++)
        ldmx4(qfh[ks], frag_addr(sb + A_QH, wid * 16, ks * 16, 144));
    {
        uint32_t st0 = sb + A_ST;
        ldmx4(khb[0], frag_addr(st0,         0, 0, 144));
        ldmx4(klb[0], frag_addr(st0 + 4608u, 0, 0, 144));
        #pragma unroll
        for (int u = 0; u < 8; u++) {
            const int ksd = u >> 1, gg = u & 1;
            if (gg == 0) ldmx4(qflc, frag_addr(sb + A_QL, wid * 16, ksd * 16, 144));
            if (u < 7) {
                const int k2 = (u + 1) >> 1, g2 = (u + 1) & 1;
                ldmx4(khb[(u + 1) & 1], frag_addr(st0,         g2 * 16, k2 * 16, 144));
                ldmx4(klb[(u + 1) & 1], frag_addr(st0 + 4608u, g2 * 16, k2 * 16, 144));
            }
            #pragma unroll
            for (int t = 0; t < 2; t++) {
                int nf = 2 * gg + t;
                mma16816(cs[nf], qfh[ksd], khb[u & 1][t], khb[u & 1][t + 2]);
                mma16816(cs[nf], qfh[ksd], klb[u & 1][t], klb[u & 1][t + 2]);
                mma16816(cs[nf], qflc,     khb[u & 1][t], khb[u & 1][t + 2]);
            }
        }
    }

    // ---- main loop ----
    for (int jb = 0; jb < 31; jb++) {
        uint32_t aph[2][4], apl[2][4];
        #pragma unroll
        for (int nf = 0; nf < 4; nf++) {
            float p0 = ex2f(cs[nf][0]), p1 = ex2f(cs[nf][1]);
            float p2 = ex2f(cs[nf][2]), p3 = ex2f(cs[nf][3]);
            rs0 += p0 + p1;
            rs1 += p2 + p3;
            uint32_t h01, l01, h23, l23;
            split_pack(p0, p1, h01, l01);
            split_pack(p2, p3, h23, l23);
            int kk = nf >> 1, base = (nf & 1) << 1;
            aph[kk][base] = h01; aph[kk][base + 1] = h23;
            apl[kk][base] = l01; apl[kk][base + 1] = l23;
            cs[nf][0] = 0.f; cs[nf][1] = 0.f; cs[nf][2] = 0.f; cs[nf][3] = 0.f;
        }
        CP_WAIT2();
        __syncthreads();
        uint32_t stN = sb + A_ST + (uint32_t)((jb + 1) & 3) * A_STSZ;  // K_{jb+1}
        uint32_t stV = sb + A_ST + (uint32_t)(jb & 3) * A_STSZ;        // V_jb

        ldmx4(khb[0], frag_addr(stN,         0, 0, 144));
        ldmx4(klb[0], frag_addr(stN + 4608u, 0, 0, 144));
        #pragma unroll
        for (int u = 0; u < 8; u++) {
            const int ksd = u >> 1, gg = u & 1;
            const int kk = u >> 2, gv = u & 3;
            uint32_t vh[4], vl[4];
            ldmx4(vh, frag_addr(stV + 9216u,  gv * 16, kk * 16, 80));
            ldmx4(vl, frag_addr(stV + 14336u, gv * 16, kk * 16, 80));
            if (gg == 0) ldmx4(qflc, frag_addr(sb + A_QL, wid * 16, ksd * 16, 144));
            #pragma unroll
            for (int t = 0; t < 2; t++) {
                int nf = 2 * gg + t;
                mma16816(cs[nf], qfh[ksd], khb[u & 1][t], khb[u & 1][t + 2]);
                mma16816(cs[nf], qfh[ksd], klb[u & 1][t], klb[u & 1][t + 2]);
                mma16816(cs[nf], qflc,     khb[u & 1][t], khb[u & 1][t + 2]);
            }
            if (u < 7) {
                const int k2 = (u + 1) >> 1, g2 = (u + 1) & 1;
                ldmx4(khb[(u + 1) & 1], frag_addr(stN,         g2 * 16, k2 * 16, 144));
                ldmx4(klb[(u + 1) & 1], frag_addr(stN + 4608u, g2 * 16, k2 * 16, 144));
            }
            #pragma unroll
            for (int t = 0; t < 2; t++) {
                int nf = 2 * gv + t;
                mma16816(yc[nf], aph[kk], vh[t], vh[t + 2]);
                mma16816(yc[nf], aph[kk], vl[t], vl[t + 2]);
                mma16816(yc[nf], apl[kk], vh[t], vh[t + 2]);
            }
        }
        __syncthreads();
        if (jb + 4 < 32) attn_load_kv(sb, jb & 3, bh, b, h, (jb + 4) * 32);
        CP_COMMIT();
    }

    // ---- final iteration (jb = 31): exp + PV only ----
    {
        uint32_t aph[2][4], apl[2][4];
        #pragma unroll
        for (int nf = 0; nf < 4; nf++) {
            float p0 = ex2f(cs[nf][0]), p1 = ex2f(cs[nf][1]);
            float p2 = ex2f(cs[nf][2]), p3 = ex2f(cs[nf][3]);
            rs0 += p0 + p1;
            rs1 += p2 + p3;
            uint32_t h01, l01, h23, l23;
            split_pack(p0, p1, h01, l01);
            split_pack(p2, p3, h23, l23);
            int kk = nf >> 1, base = (nf & 1) << 1;
            aph[kk][base] = h01; aph[kk][base + 1] = h23;
            apl[kk][base] = l01; apl[kk][base + 1] = l23;
        }
        CP_WAIT2();
        __syncthreads();
        uint32_t stV = sb + A_ST + (uint32_t)(31 & 3) * A_STSZ;
        uint32_t vhb[2][4], vlb[2][4];
        ldmx4(vhb[0], frag_addr(stV + 9216u,  0, 0, 80));
        ldmx4(vlb[0], frag_addr(stV + 14336u, 0, 0, 80));
        #pragma unroll
        for (int u = 0; u < 8; u++) {
            const int kk = u >> 2, gv = u & 3;
            if (u < 7) {
                const int k2 = (u + 1) >> 2, g2 = (u + 1) & 3;
                ldmx4(vhb[(u + 1) & 1], frag_addr(stV + 9216u,  g2 * 16, k2 * 16, 80));
                ldmx4(vlb[(u + 1) & 1], frag_addr(stV + 14336u, g2 * 16, k2 * 16, 80));
            }
            #pragma unroll
            for (int t = 0; t < 2; t++) {
                int nf = 2 * gv + t;
                mma16816(yc[nf], aph[kk], vhb[u & 1][t], vhb[u & 1][t + 2]);
                mma16816(yc[nf], aph[kk], vlb[u & 1][t], vlb[u & 1][t + 2]);
                mma16816(yc[nf], apl[kk], vhb[u & 1][t], vhb[u & 1][t + 2]);
            }
        }
    }

    // rowsum: quad reduction
    rs0 += __shfl_xor_sync(0xffffffffu, rs0, 1);
    rs0 += __shfl_xor_sync(0xffffffffu, rs0, 2);
    rs1 += __shfl_xor_sync(0xffffffffu, rs1, 1);
    rs1 += __shfl_xor_sync(0xffffffffu, rs1, 2);
    float inv0 = 1.f / rs0, inv1 = 1.f / rs1;

    int row = i0 + wid * 16 + (lane >> 2);
    #pragma unroll
    for (int nf = 0; nf < 8; nf++) {
        int d = h * DD + nf * 8 + ((lane & 3) << 1);
        uint32_t hi, lo;
        split_pack_f16(yc[nf][0] * inv0, yc[nf][1] * inv0, hi, lo);
        size_t idx = ((size_t)b * NN + row) * CC + d;
        *(uint32_t*)(g_yh + idx) = hi;
        *(uint32_t*)(g_yl + idx) = lo;
        split_pack_f16(yc[nf][2] * inv1, yc[nf][3] * inv1, hi, lo);
        idx = ((size_t)b * NN + row + 8) * CC + d;
        *(uint32_t*)(g_yh + idx) = hi;
        *(uint32_t*)(g_yl + idx) = lo;
    }
}

// ---------------- entry ----------------------------------------------------------
extern "C" void kernel_launch(void* const* d_in, const int* in_sizes, int n_in,
                              void* d_out, int out_size)
{
    const float* x  = (const float*)d_in[0];
    const float* Wq = (const float*)d_in[1];
    const float* Wk = (const float*)d_in[2];
    const float* Wv = (const float*)d_in[3];
    const float* Wo = (const float*)d_in[4];
    float* out = (float*)d_out;

    cudaFuncSetAttribute(proj_qkv_kernel, cudaFuncAttributeMaxDynamicSharedMemorySize, PROJ_SMEM);
    cudaFuncSetAttribute(proj_out_kernel, cudaFuncAttributeMaxDynamicSharedMemorySize, POUT_SMEM);
    cudaFuncSetAttribute(attn_kernel,     cudaFuncAttributeMaxDynamicSharedMemorySize, ATTN_SMEM);

    prep_w_kernel<<<dim3(CC * CC / 1024, 4), 256>>>(Wq, Wk, Wv, Wo);
    prep_x_kernel<<<dim3(NN / 32, CC / 32, BB), dim3(32, 8)>>>(x);
    proj_qkv_kernel<<<dim3(NN / 128, CC / 128, BB * 3), 256, PROJ_SMEM>>>();
    attn_kernel<<<dim3(NN / 128, BHH), 256, ATTN_SMEM>>>();
    proj_out_kernel<<<dim3(NN / 128, CC / 128, BB), 256, POUT_SMEM>>>(out);
}